// round 5
// baseline (speedup 1.0000x reference)
#include <cuda_runtime.h>
#include <cuda_bf16.h>

#define N_MAX 100000
#define NF 128
#define NH 64
#define NC 16
#define CAP 48
#define OVF_CAP (1 << 20)

// Scratch (alloc-free rule: __device__ globals)
__device__ float g_h0[N_MAX * NH];     // x @ W1
__device__ float g_h1[N_MAX * NH];     // aggregated layer 1
__device__ float g_h2[N_MAX * NC];     // relu(h1) @ W2
__device__ int2  g_bkt1[N_MAX * CAP];  // (src, w-bits) per dst, layer 1
__device__ int2  g_bkt2[N_MAX * CAP];
__device__ int   g_cnt1[N_MAX];
__device__ int   g_cnt2[N_MAX];
__device__ int   g_ovf_cnt[2];
__device__ int3  g_ovf1[OVF_CAP];
__device__ int3  g_ovf2[OVF_CAP];

// ---------------- packed f32x2 helpers -------------------------------------
__device__ __forceinline__ unsigned long long pk2(float lo, float hi) {
    unsigned long long r;
    asm("mov.b64 %0, {%1, %2};" : "=l"(r) : "f"(lo), "f"(hi));
    return r;
}
__device__ __forceinline__ void fma2(unsigned long long& d,
                                     unsigned long long a, unsigned long long b) {
    asm("fma.rn.f32x2 %0, %1, %2, %0;" : "+l"(d) : "l"(a), "l"(b));
}
__device__ __forceinline__ float2 upk2(unsigned long long v) {
    float2 f;
    asm("mov.b64 {%0, %1}, %2;" : "=f"(f.x), "=f"(f.y) : "l"(v));
    return f;
}

// ---------------------------------------------------------------------------
// GEMM1: h0 = x @ W1 using packed fma.rn.f32x2 (2 fp32 FMA lanes / instr).
// Also zeroes g_cnt1/g_cnt2/overflow counters (runs before bin kernels).
// Block 256, tile 64x64, per-thread 4 rows (2 f32x2 row-pairs) x 4 cols.
// ---------------------------------------------------------------------------
__global__ void __launch_bounds__(256) gemm1_kernel(
    const float* __restrict__ x, const float* __restrict__ W1, int n)
{
    __shared__ float ws[NF * NH];    // [k][c], 32 KB
    __shared__ float xs[32 * 68];    // [k_local][row], stride 68 (16B-aligned rows)

    int tid = threadIdx.x;
    #pragma unroll
    for (int i = tid; i < NF * NH / 4; i += 256)
        ((float4*)ws)[i] = ((const float4*)W1)[i];

    int row0 = blockIdx.x * 64;
    // fused zeroing of per-layer bucket counters
    {
        int z = row0 + (tid & 63);
        if (tid < 64 && z < n) { g_cnt1[z] = 0; g_cnt2[z] = 0; }
        if (blockIdx.x == 0 && tid == 64) { g_ovf_cnt[0] = 0; g_ovf_cnt[1] = 0; }
    }

    int tx = tid & 15, ty = tid >> 4;
    int r0 = ty * 4, c0 = tx * 4;
    int kq = tid & 7;
    int lrow = tid >> 3;

    unsigned long long acc[2][4] = {};   // [rowpair][col], bits {0f,0f}

    for (int kc = 0; kc < 4; kc++) {
        __syncthreads();
        #pragma unroll
        for (int pass = 0; pass < 2; pass++) {
            int row = lrow + pass * 32;
            int grow = row0 + row;
            float4 v = make_float4(0.f, 0.f, 0.f, 0.f);
            if (grow < n)
                v = *(const float4*)&x[grow * NF + kc * 32 + kq * 4];
            xs[(kq * 4 + 0) * 68 + row] = v.x;
            xs[(kq * 4 + 1) * 68 + row] = v.y;
            xs[(kq * 4 + 2) * 68 + row] = v.z;
            xs[(kq * 4 + 3) * 68 + row] = v.w;
        }
        __syncthreads();
        #pragma unroll
        for (int kk = 0; kk < 32; kk++) {
            float4 b = *(const float4*)&ws[(kc * 32 + kk) * NH + c0];
            float4 a = *(const float4*)&xs[kk * 68 + r0];
            unsigned long long a01 = pk2(a.x, a.y);
            unsigned long long a23 = pk2(a.z, a.w);
            unsigned long long b0 = pk2(b.x, b.x);
            unsigned long long b1 = pk2(b.y, b.y);
            unsigned long long b2 = pk2(b.z, b.z);
            unsigned long long b3 = pk2(b.w, b.w);
            fma2(acc[0][0], a01, b0); fma2(acc[1][0], a23, b0);
            fma2(acc[0][1], a01, b1); fma2(acc[1][1], a23, b1);
            fma2(acc[0][2], a01, b2); fma2(acc[1][2], a23, b2);
            fma2(acc[0][3], a01, b3); fma2(acc[1][3], a23, b3);
        }
    }

    #pragma unroll
    for (int rp = 0; rp < 2; rp++) {
        float2 c0v = upk2(acc[rp][0]);
        float2 c1v = upk2(acc[rp][1]);
        float2 c2v = upk2(acc[rp][2]);
        float2 c3v = upk2(acc[rp][3]);
        int gr0 = row0 + r0 + 2 * rp;
        if (gr0 < n)
            *(float4*)&g_h0[gr0 * NH + c0] = make_float4(c0v.x, c1v.x, c2v.x, c3v.x);
        if (gr0 + 1 < n)
            *(float4*)&g_h0[(gr0 + 1) * NH + c0] = make_float4(c0v.y, c1v.y, c2v.y, c3v.y);
    }
}

// ---------------------------------------------------------------------------
// Binning: edge e (src=ei[e], dst=ei[E+e], w=ew[e]) goes into dst's bucket.
// Overflow (deg > CAP) edges go to an overflow list, applied with atomics later.
// ---------------------------------------------------------------------------
template <int LAYER>
__global__ void __launch_bounds__(256) bin_kernel(
    const int* __restrict__ ei, const float* __restrict__ ew, int E)
{
    int e = blockIdx.x * 256 + threadIdx.x;
    if (e >= E) return;
    int   s = __ldg(&ei[e]);
    int   d = __ldg(&ei[E + e]);
    float w = __ldg(&ew[e]);

    int* cnt   = (LAYER == 0) ? g_cnt1 : g_cnt2;
    int2* bkt  = (LAYER == 0) ? g_bkt1 : g_bkt2;
    int3* ovf  = (LAYER == 0) ? g_ovf1 : g_ovf2;

    int pos = atomicAdd(&cnt[d], 1);
    if (pos < CAP) {
        bkt[d * CAP + pos] = make_int2(s, __float_as_int(w));
    } else {
        int o = atomicAdd(&g_ovf_cnt[LAYER], 1);
        if (o < OVF_CAP) ovf[o] = make_int3(s, d, __float_as_int(w));
    }
}

// ---------------------------------------------------------------------------
// Aggregate layer 1: one warp per node. Lane holds 2 of 64 output floats.
// Edge metadata preloaded to registers, broadcast by shfl; gathers unrolled x4.
// Plain store of the full row — no atomics.
// ---------------------------------------------------------------------------
__global__ void __launch_bounds__(256) agg1_kernel(int n)
{
    int wid  = (blockIdx.x * 256 + threadIdx.x) >> 5;
    int lane = threadIdx.x & 31;
    if (wid >= n) return;

    int c = g_cnt1[wid];
    if (c > CAP) c = CAP;
    const int2* bp = g_bkt1 + wid * CAP;

    int2 m0 = make_int2(0, 0), m1 = make_int2(0, 0);
    if (lane < c)       m0 = __ldg(&bp[lane]);
    if (lane + 32 < c)  m1 = __ldg(&bp[lane + 32]);

    float2 acc = make_float2(0.f, 0.f);
    int c32 = c < 32 ? c : 32;
    int e = 0;
    for (; e + 4 <= c32; e += 4) {
        float2 v[4]; float wt[4];
        #pragma unroll
        for (int u = 0; u < 4; u++) {
            int s = __shfl_sync(0xffffffffu, m0.x, e + u);
            wt[u] = __int_as_float(__shfl_sync(0xffffffffu, m0.y, e + u));
            v[u]  = __ldg((const float2*)(g_h0 + s * NH) + lane);
        }
        #pragma unroll
        for (int u = 0; u < 4; u++) {
            acc.x += wt[u] * v[u].x;
            acc.y += wt[u] * v[u].y;
        }
    }
    for (; e < c32; e++) {
        int s = __shfl_sync(0xffffffffu, m0.x, e);
        float wt = __int_as_float(__shfl_sync(0xffffffffu, m0.y, e));
        float2 v = __ldg((const float2*)(g_h0 + s * NH) + lane);
        acc.x += wt * v.x; acc.y += wt * v.y;
    }
    for (int e2 = 32; e2 < c; e2++) {
        int s = __shfl_sync(0xffffffffu, m1.x, e2 - 32);
        float wt = __int_as_float(__shfl_sync(0xffffffffu, m1.y, e2 - 32));
        float2 v = __ldg((const float2*)(g_h0 + s * NH) + lane);
        acc.x += wt * v.x; acc.y += wt * v.y;
    }

    ((float2*)(g_h1 + wid * NH))[lane] = acc;
}

// ---------------------------------------------------------------------------
// Overflow apply (layer 1): atomics into g_h1 AFTER agg1's plain stores.
// Expected count: 0. Fixed small grid; reads device-side counter.
// ---------------------------------------------------------------------------
__global__ void __launch_bounds__(256) ovf1_kernel()
{
    int tot = g_ovf_cnt[0];
    if (tot > OVF_CAP) tot = OVF_CAP;
    for (int i = blockIdx.x * 256 + threadIdx.x; i < tot; i += gridDim.x * 256) {
        int3 o = g_ovf1[i];
        float w = __int_as_float(o.z);
        #pragma unroll
        for (int j = 0; j < NH / 4; j++) {
            float4 v = *(const float4*)(g_h0 + o.x * NH + j * 4);
            asm volatile("red.global.add.v4.f32 [%0], {%1,%2,%3,%4};"
                         :: "l"(&g_h1[o.y * NH + j * 4]),
                            "f"(v.x * w), "f"(v.y * w), "f"(v.z * w), "f"(v.w * w)
                         : "memory");
        }
    }
}

// ---------------------------------------------------------------------------
// GEMM2: h2[n,16] = relu(h1[n,64]) @ W2[64,16].
// ---------------------------------------------------------------------------
__global__ void __launch_bounds__(256) gemm2_kernel(
    const float* __restrict__ W2, int n)
{
    __shared__ float ws[NH * NC];
    __shared__ float hs[64 * 65];

    int tid = threadIdx.x;
    #pragma unroll
    for (int i = tid; i < NH * NC / 4; i += 256)
        ((float4*)ws)[i] = ((const float4*)W2)[i];

    int row0 = blockIdx.x * 64;
    #pragma unroll
    for (int idx = tid; idx < 64 * 64; idx += 256) {
        int r = idx >> 6, k = idx & 63;
        int grow = row0 + r;
        float v = 0.f;
        if (grow < n) v = g_h1[grow * NH + k];
        hs[r * 65 + k] = fmaxf(v, 0.f);   // fused ReLU
    }
    __syncthreads();

    int cg = tid & 3, r = tid >> 2;
    float a0 = 0.f, a1 = 0.f, a2 = 0.f, a3 = 0.f;
    #pragma unroll
    for (int k = 0; k < NH; k++) {
        float a = hs[r * 65 + k];
        float4 b = *(const float4*)&ws[k * NC + cg * 4];
        a0 += a * b.x; a1 += a * b.y; a2 += a * b.z; a3 += a * b.w;
    }

    int grow = row0 + r;
    if (grow < n)
        *(float4*)&g_h2[grow * NC + cg * 4] = make_float4(a0, a1, a2, a3);
}

// ---------------------------------------------------------------------------
// Aggregate layer 2: 8-lane group per node (lane holds 2 of 16 floats).
// Writes the output row with a plain store (covers out fully, incl. deg-0).
// ---------------------------------------------------------------------------
__global__ void __launch_bounds__(256) agg2_kernel(float* __restrict__ out, int n)
{
    int tid = threadIdx.x;
    int node = (blockIdx.x * 256 + tid) >> 3;
    int sub  = tid & 7;
    if (node >= n) return;

    int c = g_cnt2[node];
    if (c > CAP) c = CAP;
    const int2* bp = g_bkt2 + node * CAP;

    float2 acc = make_float2(0.f, 0.f);
    int e = 0;
    for (; e + 4 <= c; e += 4) {
        int2 m[4];
        #pragma unroll
        for (int u = 0; u < 4; u++) m[u] = __ldg(&bp[e + u]);
        float2 v[4];
        #pragma unroll
        for (int u = 0; u < 4; u++)
            v[u] = __ldg((const float2*)(g_h2 + m[u].x * NC) + sub);
        #pragma unroll
        for (int u = 0; u < 4; u++) {
            float wt = __int_as_float(m[u].y);
            acc.x += wt * v[u].x;
            acc.y += wt * v[u].y;
        }
    }
    for (; e < c; e++) {
        int2 m = __ldg(&bp[e]);
        float wt = __int_as_float(m.y);
        float2 v = __ldg((const float2*)(g_h2 + m.x * NC) + sub);
        acc.x += wt * v.x; acc.y += wt * v.y;
    }

    ((float2*)(out + node * NC))[sub] = acc;
}

// ---------------------------------------------------------------------------
__global__ void __launch_bounds__(256) ovf2_kernel(float* __restrict__ out)
{
    int tot = g_ovf_cnt[1];
    if (tot > OVF_CAP) tot = OVF_CAP;
    for (int i = blockIdx.x * 256 + threadIdx.x; i < tot; i += gridDim.x * 256) {
        int3 o = g_ovf2[i];
        float w = __int_as_float(o.z);
        #pragma unroll
        for (int j = 0; j < NC / 4; j++) {
            float4 v = *(const float4*)(g_h2 + o.x * NC + j * 4);
            asm volatile("red.global.add.v4.f32 [%0], {%1,%2,%3,%4};"
                         :: "l"(&out[o.y * NC + j * 4]),
                            "f"(v.x * w), "f"(v.y * w), "f"(v.z * w), "f"(v.w * w)
                         : "memory");
        }
    }
}

// ---------------------------------------------------------------------------
extern "C" void kernel_launch(void* const* d_in, const int* in_sizes, int n_in,
                              void* d_out, int out_size)
{
    const float* x   = (const float*)d_in[0];
    const int*   ei1 = (const int*)  d_in[1];
    const int*   ei2 = (const int*)  d_in[2];
    const float* ew1 = (const float*)d_in[3];
    const float* ew2 = (const float*)d_in[4];
    const float* W1  = (const float*)d_in[5];
    const float* W2  = (const float*)d_in[6];
    float* out = (float*)d_out;

    int n  = in_sizes[0] / NF;
    int E1 = in_sizes[3];
    int E2 = in_sizes[4];
    int nb = (n + 63) / 64;

    gemm1_kernel<<<nb, 256>>>(x, W1, n);                       // also zeroes counters
    bin_kernel<0><<<(E1 + 255) / 256, 256>>>(ei1, ew1, E1);
    bin_kernel<1><<<(E2 + 255) / 256, 256>>>(ei2, ew2, E2);
    agg1_kernel<<<(n * 32 + 255) / 256, 256>>>(n);
    ovf1_kernel<<<16, 256>>>();
    gemm2_kernel<<<nb, 256>>>(W2, n);
    agg2_kernel<<<(n * 8 + 255) / 256, 256>>>(out, n);
    ovf2_kernel<<<16, 256>>>(out);
}